// round 17
// baseline (speedup 1.0000x reference)
#include <cuda_runtime.h>
#include <cuda_fp16.h>
#include <cstdint>
#include <cstddef>

// ------------------- problem constants -------------------
#define HD    2048        // hidden dim H
#define KTOT  14336       // 8192 + 4096 + 1024 + 1024
#define NR    8192        // rows of x / output
#define LN_EPS 1e-5f

#define SWZ128(off) ((off) ^ (((off) >> 3) & 0x70))

// ------------------- device scratch (no allocs allowed) -------------------
__device__ __half g_A [(size_t)HD * KTOT];   // concat D (fp16)       [2048 x 14336]
__device__ __half g_B [(size_t)HD * KTOT];   // (W*scale)^T (fp16)    [2048 x 14336]
__device__ __half g_x [(size_t)NR * HD];     // x (fp16)              [8192 x 2048]
__device__ __half g_M [(size_t)HD * HD];     // M (fp16)              [2048 x 2048]
__device__ float  g_h [(size_t)NR * HD];     // pre-LN activations

// ------------------- PTX helpers -------------------
__device__ __forceinline__ uint32_t smem_u32(const void* p) {
    uint32_t a;
    asm("{ .reg .u64 t; cvta.to.shared.u64 t, %1; cvt.u32.u64 %0, t; }" : "=r"(a) : "l"(p));
    return a;
}

__device__ __forceinline__ void cp_async16(uint32_t saddr, const void* gaddr) {
    asm volatile("cp.async.cg.shared.global [%0], [%1], 16;" :: "r"(saddr), "l"(gaddr));
}

__device__ __forceinline__ void ldsm4(uint32_t* r, uint32_t addr) {
    asm volatile("ldmatrix.sync.aligned.m8n8.x4.shared.b16 {%0,%1,%2,%3}, [%4];"
                 : "=r"(r[0]), "=r"(r[1]), "=r"(r[2]), "=r"(r[3]) : "r"(addr));
}

__device__ __forceinline__ void mma_fp16(float* c, const uint32_t* a, const uint32_t* b) {
    asm volatile(
        "mma.sync.aligned.m16n8k16.row.col.f32.f16.f16.f32 "
        "{%0,%1,%2,%3}, {%4,%5,%6,%7}, {%8,%9}, {%0,%1,%2,%3};"
        : "+f"(c[0]), "+f"(c[1]), "+f"(c[2]), "+f"(c[3])
        : "r"(a[0]), "r"(a[1]), "r"(a[2]), "r"(a[3]), "r"(b[0]), "r"(b[1]));
}

__device__ __forceinline__ uint2 pack4half(float a, float b, float c, float d) {
    __half2 lo = __halves2half2(__float2half(a), __float2half(b));
    __half2 hi = __halves2half2(__float2half(c), __float2half(d));
    uint2 r;
    r.x = *reinterpret_cast<uint32_t*>(&lo);
    r.y = *reinterpret_cast<uint32_t*>(&hi);
    return r;
}

// ------------------- prep kernels -------------------

// x -> fp16, 8 elems / thread (16B store)
__global__ void split_x_kernel(const float* __restrict__ src) {
    size_t i = ((size_t)blockIdx.x * blockDim.x + threadIdx.x) * 8;
    float4 v0 = *reinterpret_cast<const float4*>(src + i);
    float4 v1 = *reinterpret_cast<const float4*>(src + i + 4);
    uint4 o;
    uint2 a = pack4half(v0.x, v0.y, v0.z, v0.w);
    uint2 b = pack4half(v1.x, v1.y, v1.z, v1.w);
    o.x = a.x; o.y = a.y; o.z = b.x; o.w = b.y;
    *reinterpret_cast<uint4*>(g_x + i) = o;
}

// D matrix [HD, P] -> concat A plane at column offset colbase, 8 elems / thread
__global__ void splitcat_kernel(const float* __restrict__ src, int pshift, int colbase) {
    size_t i = ((size_t)blockIdx.x * blockDim.x + threadIdx.x) * 8;
    size_t j = i >> pshift;
    int    p = (int)(i & (size_t)((1 << pshift) - 1));
    float4 v0 = *reinterpret_cast<const float4*>(src + i);
    float4 v1 = *reinterpret_cast<const float4*>(src + i + 4);
    uint4 o;
    uint2 a = pack4half(v0.x, v0.y, v0.z, v0.w);
    uint2 b = pack4half(v1.x, v1.y, v1.z, v1.w);
    o.x = a.x; o.y = a.y; o.z = b.x; o.w = b.y;
    *reinterpret_cast<uint4*>(g_A + j * KTOT + colbase + p) = o;
}

// transpose + block-scale ALL W matrices into B [HD, KTOT].
__global__ void wtrans_all_kernel(const float* __restrict__ w_qkv, const float* __restrict__ s_qkv,
                                  const float* __restrict__ w_z,   const float* __restrict__ s_z,
                                  const float* __restrict__ w_b,   const float* __restrict__ s_b,
                                  const float* __restrict__ w_a,   const float* __restrict__ s_a) {
    __shared__ float t[128][33];
    int n0  = blockIdx.x * 32;         // HD index
    int gp0 = blockIdx.y * 128;        // global concat-K index (128-aligned)

    const float* W; const float* S; int lp0;
    if      (gp0 < 8192)  { W = w_qkv; S = s_qkv; lp0 = gp0;         }
    else if (gp0 < 12288) { W = w_z;   S = s_z;   lp0 = gp0 - 8192;  }
    else if (gp0 < 13312) { W = w_b;   S = s_b;   lp0 = gp0 - 12288; }
    else                  { W = w_a;   S = s_a;   lp0 = gp0 - 13312; }

    int tx = threadIdx.x, ty = threadIdx.y;       // block (32, 8)
    float sc = S[(lp0 >> 7) * (HD >> 7) + (n0 >> 7)];

    #pragma unroll
    for (int r = 0; r < 16; ++r)
        t[ty + r * 8][tx] = W[(size_t)(lp0 + ty + r * 8) * HD + n0 + tx];
    __syncthreads();

    #pragma unroll
    for (int r = 0; r < 4; ++r) {
        int nl = ty + r * 8;
        float v0 = t[4 * tx]     [nl] * sc;
        float v1 = t[4 * tx + 1] [nl] * sc;
        float v2 = t[4 * tx + 2] [nl] * sc;
        float v3 = t[4 * tx + 3] [nl] * sc;
        *reinterpret_cast<uint2*>(g_B + (size_t)(n0 + nl) * KTOT + gp0 + 4 * tx) =
            pack4half(v0, v1, v2, v3);
    }
}

// ------------------- main GEMM (single fp16 product, templated N tile) -------------------
// BM = 128 fixed; BN = 256 (GEMM1) or 128 (GEMM2). Warps 2(M) x 4(N), warp tile 64 x BN/4.
// K-chunk 128 as two 64-col sub-tiles, each with its own cp.async commit group.
// mode 0:  M = A . B^T over K=KTOT, write fp16 g_M
// mode 1:  h = x . M^T over K=HD,   write fp32 g_h
template <int BN>
__global__ void __launch_bounds__(256, 1) gemm_kernel(int mode) {
    constexpr int NJ     = BN / 32;           // n8-tiles per warp (8 or 4)
    constexpr int SUB_A  = 128 * 128;         // A sub-tile bytes
    constexpr int SUB_B  = BN * 128;          // B sub-tile bytes
    constexpr int TILE_A = 2 * SUB_A;
    constexpr int STAGE  = 2 * (SUB_A + SUB_B);
    constexpr int CHUNK_K = 128;

    const __half *A, *B;
    int K;
    if (mode == 0) { A = g_A; B = g_B; K = KTOT; }
    else           { A = g_x; B = g_M; K = HD;   }

    extern __shared__ __align__(1024) char smem[];
    const uint32_t sb = smem_u32(smem);

    const int tid = threadIdx.x;
    const int wid = tid >> 5;
    const int lid = tid & 31;
    const int m0 = blockIdx.y * 128;          // output rows  (A rows)
    const int n0 = blockIdx.x * BN;           // output cols  (B rows)
    const int wm = (wid & 1) * 64;            // warp row offset
    const int wn = (wid >> 1) * (BN / 4);     // warp col offset

    const int NC = K / CHUNK_K;

    // ---- sub-tile loader: loads 64 k-cols of A and B, own commit group ----
    auto load_sub = [&](int c, int s, int s2) {
        const int k0 = c * CHUNK_K + s2 * 64;
        const uint32_t stage = sb + s * STAGE;
        const uint32_t aBase = stage + s2 * SUB_A;
        const uint32_t bBase = stage + TILE_A + s2 * SUB_B;
        #pragma unroll
        for (int i = 0; i < 4; ++i) {               // A: 128 rows x 128 B
            int idx = tid + i * 256;
            int row = idx >> 3;
            int seg = idx & 7;
            uint32_t sw = SWZ128((uint32_t)(row * 128 + seg * 16));
            cp_async16(aBase + sw, A + (size_t)(m0 + row) * K + k0 + seg * 8);
        }
        #pragma unroll
        for (int i = 0; i < NJ; ++i) {              // B: BN rows x 128 B
            int idx = tid + i * 256;
            int row = idx >> 3;
            int seg = idx & 7;
            uint32_t sw = SWZ128((uint32_t)(row * 128 + seg * 16));
            cp_async16(bBase + sw, B + (size_t)(n0 + row) * K + k0 + seg * 8);
        }
        asm volatile("cp.async.commit_group;" ::: "memory");
    };

    // prologue: chunk 0 as two groups
    load_sub(0, 0, 0);
    load_sub(0, 0, 1);

    float acc[4][NJ][4];
    #pragma unroll
    for (int i = 0; i < 4; ++i)
        #pragma unroll
        for (int j = 0; j < NJ; ++j)
            #pragma unroll
            for (int q = 0; q < 4; ++q) acc[i][j][q] = 0.f;

    const int lrow = lid & 7;
    const int lmat = lid >> 3;

    // compute one 64-col sub-tile (4 ksteps)
    auto compute_sub = [&](uint32_t stage, int s2) {
        const uint32_t tA = stage + s2 * SUB_A;
        const uint32_t tB = stage + TILE_A + s2 * SUB_B;
        #pragma unroll
        for (int ks = 0; ks < 4; ++ks) {
            const int kb = ks * 32;
            uint32_t bf[NJ][2];
            #pragma unroll
            for (int jp = 0; jp < NJ / 2; ++jp) {
                int brow = wn + jp * 16 + ((lmat >> 1) ? 8 : 0) + lrow;
                int bcol = kb + ((lmat & 1) ? 16 : 0);
                uint32_t r[4];
                ldsm4(r, tB + SWZ128((uint32_t)(brow * 128 + bcol)));
                bf[jp * 2 + 0][0] = r[0]; bf[jp * 2 + 0][1] = r[1];
                bf[jp * 2 + 1][0] = r[2]; bf[jp * 2 + 1][1] = r[3];
            }
            uint32_t af[4][4];
            #pragma unroll
            for (int i = 0; i < 4; ++i) {
                int arow = wm + i * 16 + ((lmat & 1) ? 8 : 0) + lrow;
                int acol = kb + ((lmat & 2) ? 16 : 0);
                ldsm4(af[i], tA + SWZ128((uint32_t)(arow * 128 + acol)));
            }
            #pragma unroll
            for (int i = 0; i < 4; ++i)
                #pragma unroll
                for (int j = 0; j < NJ; ++j)
                    mma_fp16(acc[i][j], af[i], bf[j]);
        }
    };

    for (int c = 0; c < NC; ++c) {
        const uint32_t stage = sb + (c & 1) * STAGE;
        const bool more = (c + 1 < NC);

        // sub-tile 0 of chunk c has landed when <=1 newer group pending
        asm volatile("cp.async.wait_group 1;" ::: "memory");
        __syncthreads();

        if (more) {
            load_sub(c + 1, (c + 1) & 1, 0);
            load_sub(c + 1, (c + 1) & 1, 1);
        }

        compute_sub(stage, 0);

        // sub-tile 1 of chunk c: pending groups beyond it = the 2 prefetches (if any)
        if (more) asm volatile("cp.async.wait_group 2;" ::: "memory");
        else      asm volatile("cp.async.wait_group 0;" ::: "memory");
        __syncthreads();

        compute_sub(stage, 1);
    }

    // ---- epilogue: write accumulators ----
    const int g = lid >> 2;
    const int t4 = lid & 3;
    #pragma unroll
    for (int i = 0; i < 4; ++i) {
        #pragma unroll
        for (int j = 0; j < NJ; ++j) {
            int row = m0 + wm + i * 16 + g;
            int col = n0 + wn + j * 8 + 2 * t4;
            if (mode == 1) {
                float2 v0 = make_float2(acc[i][j][0], acc[i][j][1]);
                float2 v1 = make_float2(acc[i][j][2], acc[i][j][3]);
                *reinterpret_cast<float2*>(g_h + (size_t)row * HD + col) = v0;
                *reinterpret_cast<float2*>(g_h + (size_t)(row + 8) * HD + col) = v1;
            } else {
                __half2 v0 = __halves2half2(__float2half(acc[i][j][0]),
                                            __float2half(acc[i][j][1]));
                __half2 v1 = __halves2half2(__float2half(acc[i][j][2]),
                                            __float2half(acc[i][j][3]));
                *reinterpret_cast<__half2*>(g_M + (size_t)row * HD + col) = v0;
                *reinterpret_cast<__half2*>(g_M + (size_t)(row + 8) * HD + col) = v1;
            }
        }
    }
}

// smem sizes per instantiation
#define SMEM_REQ_256 (2 * (2 * (128 * 128) + 2 * (256 * 128)))   // 192 KB
#define SMEM_REQ_128 (2 * (2 * (128 * 128) + 2 * (128 * 128)))   // 128 KB

// ------------------- LayerNorm -------------------
__global__ void ln_kernel(const float* __restrict__ gamma, const float* __restrict__ beta,
                          float* __restrict__ out) {
    const int r = blockIdx.x;
    const int tid = threadIdx.x;      // 256 threads, 8 floats each
    const float* row = g_h + (size_t)r * HD;
    float4 a = *reinterpret_cast<const float4*>(row + tid * 4);
    float4 b = *reinterpret_cast<const float4*>(row + 1024 + tid * 4);
    float s = a.x + a.y + a.z + a.w + b.x + b.y + b.z + b.w;
    float q = a.x * a.x + a.y * a.y + a.z * a.z + a.w * a.w
            + b.x * b.x + b.y * b.y + b.z * b.z + b.w * b.w;
    #pragma unroll
    for (int o = 16; o; o >>= 1) {
        s += __shfl_xor_sync(0xFFFFFFFFu, s, o);
        q += __shfl_xor_sync(0xFFFFFFFFu, q, o);
    }
    __shared__ float ss[8], qq[8];
    __shared__ float mu_s, ri_s;
    if ((tid & 31) == 0) { ss[tid >> 5] = s; qq[tid >> 5] = q; }
    __syncthreads();
    if (tid == 0) {
        float S = 0.f, Q = 0.f;
        #pragma unroll
        for (int i = 0; i < 8; ++i) { S += ss[i]; Q += qq[i]; }
        float mu = S / (float)HD;
        float var = Q / (float)HD - mu * mu;
        mu_s = mu;
        ri_s = rsqrtf(var + LN_EPS);
    }
    __syncthreads();
    const float mu = mu_s, ri = ri_s;
    float4 g1 = *reinterpret_cast<const float4*>(gamma + tid * 4);
    float4 b1 = *reinterpret_cast<const float4*>(beta + tid * 4);
    float4 g2 = *reinterpret_cast<const float4*>(gamma + 1024 + tid * 4);
    float4 b2 = *reinterpret_cast<const float4*>(beta + 1024 + tid * 4);
    float4 o1, o2;
    o1.x = (a.x - mu) * ri * g1.x + b1.x;
    o1.y = (a.y - mu) * ri * g1.y + b1.y;
    o1.z = (a.z - mu) * ri * g1.z + b1.z;
    o1.w = (a.w - mu) * ri * g1.w + b1.w;
    o2.x = (b.x - mu) * ri * g2.x + b2.x;
    o2.y = (b.y - mu) * ri * g2.y + b2.y;
    o2.z = (b.z - mu) * ri * g2.z + b2.z;
    o2.w = (b.w - mu) * ri * g2.w + b2.w;
    float* orow = out + (size_t)r * HD;
    *reinterpret_cast<float4*>(orow + tid * 4) = o1;
    *reinterpret_cast<float4*>(orow + 1024 + tid * 4) = o2;
}

// ------------------- launch -------------------
extern "C" void kernel_launch(void* const* d_in, const int* in_sizes, int n_in,
                              void* d_out, int out_size) {
    const float* x     = (const float*)d_in[0];
    const float* w_qkv = (const float*)d_in[1];
    const float* s_qkv = (const float*)d_in[2];
    const float* w_z   = (const float*)d_in[3];
    const float* s_z   = (const float*)d_in[4];
    const float* w_b   = (const float*)d_in[5];
    const float* s_b   = (const float*)d_in[6];
    const float* w_a   = (const float*)d_in[7];
    const float* s_a   = (const float*)d_in[8];
    const float* d_qkv = (const float*)d_in[9];
    const float* d_z   = (const float*)d_in[10];
    const float* d_b   = (const float*)d_in[11];
    const float* d_a   = (const float*)d_in[12];
    const float* gamma = (const float*)d_in[13];
    const float* beta  = (const float*)d_in[14];
    float* out = (float*)d_out;

    cudaFuncSetAttribute(gemm_kernel<256>, cudaFuncAttributeMaxDynamicSharedMemorySize,
                         SMEM_REQ_256);
    cudaFuncSetAttribute(gemm_kernel<128>, cudaFuncAttributeMaxDynamicSharedMemorySize,
                         SMEM_REQ_128);

    // launches 1-4: concat D matrices into A (col bases: 0, 8192, 12288, 13312)
    splitcat_kernel<<<(HD * 8192) / 2048, 256>>>(d_qkv, 13, 0);
    splitcat_kernel<<<(HD * 4096) / 2048, 256>>>(d_z,   12, 8192);
    splitcat_kernel<<<(HD * 1024) / 2048, 256>>>(d_b,   10, 12288);
    splitcat_kernel<<<(HD * 1024) / 2048, 256>>>(d_a,   10, 13312);

    // launch 5: transpose + scale all W matrices into B (single launch)
    wtrans_all_kernel<<<dim3(HD / 32, KTOT / 128), dim3(32, 8)>>>(
        w_qkv, s_qkv, w_z, s_z, w_b, s_b, w_a, s_a);

    // launch 6: GEMM1  M = A . B^T (K = 14336), 128x256 tiles -> 128 CTAs = one wave
    gemm_kernel<256><<<dim3(HD / 256, HD / 128), 256, SMEM_REQ_256>>>(0);

    // launch 7: x -> fp16
    split_x_kernel<<<(NR * HD) / 2048, 256>>>(x);

    // launch 8: GEMM2  h = x . M^T (K = 2048), 128x128 tiles -> 1024 CTAs (~7 waves)
    gemm_kernel<128><<<dim3(HD / 128, NR / 128), 256, SMEM_REQ_128>>>(1);

    // launch 9: LayerNorm
    ln_kernel<<<NR, 256>>>(gamma, beta, out);
}